// round 10
// baseline (speedup 1.0000x reference)
#include <cuda_runtime.h>
#include <cuda_bf16.h>

#define N_NODES 100000
#define N_EDGES 1600000

// ---------------- scratch: __device__ globals --------------------------------
__device__ __align__(16) float g_h[N_NODES * 64];     // GEMM output / gather src
__device__ __align__(16) float g_agg[N_NODES * 64];   // aggregation output
__device__ float g_dinv[N_NODES];
__device__ int   g_deg[N_NODES];
__device__ int   g_cur[N_NODES];
__device__ int   g_off[N_NODES + 1];
__device__ int   g_src[N_EDGES];
__device__ int   g_dst[N_EDGES];
__device__ int   g_csrc[N_EDGES];
__device__ int   g_is64;

// ---------------- zero + dtype detect ----------------------------------------
// int64 edge values < 2^31 => every odd 32-bit word is 0. int32 uniform in
// [0,100000): 256 odd words all zero has P ~ 1e-1280.
__global__ void k_zero(const int* __restrict__ ei) {
    int i = blockIdx.x * blockDim.x + threadIdx.x;
    if (i < N_NODES) { g_deg[i] = 0; g_cur[i] = 0; }
    if (blockIdx.x == 0) {
        __shared__ int nonzero;
        if (threadIdx.x == 0) nonzero = 0;
        __syncthreads();
        if (ei[2 * threadIdx.x + 1] != 0) atomicAdd(&nonzero, 1);
        __syncthreads();
        if (threadIdx.x == 0) g_is64 = (nonzero == 0) ? 1 : 0;
    }
}

// ---------------- decode edges + degree count (fused) ------------------------
__global__ void k_pre(const int* __restrict__ ei) {
    int e = blockIdx.x * blockDim.x + threadIdx.x;
    if (e >= N_EDGES) return;
    int s, d;
    if (g_is64) { s = ei[2 * e]; d = ei[2 * (N_EDGES + e)]; }
    else        { s = ei[e];     d = ei[N_EDGES + e]; }
    if ((unsigned)s >= N_NODES) s = 0;
    if ((unsigned)d >= N_NODES) d = 0;
    g_src[e] = s;
    g_dst[e] = d;
    atomicAdd(&g_deg[d], 1);
}

// ---------------- prefix scan of degrees -> offsets, plus dinv ---------------
__global__ void k_scan() {
    __shared__ int partial[1024];
    const int tid = threadIdx.x;
    const int chunk = (N_NODES + 1023) / 1024;  // 98
    const int start = tid * chunk;
    const int end = min(start + chunk, N_NODES);

    int s = 0;
    for (int i = start; i < end; i++) s += g_deg[i];
    partial[tid] = s;
    __syncthreads();

    for (int off = 1; off < 1024; off <<= 1) {
        int v = 0;
        if (tid >= off) v = partial[tid - off];
        __syncthreads();
        partial[tid] += v;
        __syncthreads();
    }

    int run = (tid > 0) ? partial[tid - 1] : 0;  // exclusive base
    for (int i = start; i < end; i++) {
        g_off[i] = run;
        int dg = g_deg[i];
        run += dg;
        g_dinv[i] = rsqrtf((float)(dg + 1));  // +1: self-loop
    }
    if (start < N_NODES && end == N_NODES) g_off[N_NODES] = run;
}

// ---------------- edge placement into CSR (src index only) -------------------
__global__ void k_place() {
    int e = blockIdx.x * blockDim.x + threadIdx.x;
    if (e < N_EDGES) {
        int d = g_dst[e];
        int pos = g_off[d] + atomicAdd(&g_cur[d], 1);
        g_csrc[pos] = g_src[e];
    }
}

// ---------------- GEMM: [ROWS rows] x [64 -> OUT], 4x4 per thread ------------
// FROM_X: input from param x; else from g_agg with ReLU fused into the load.
template <int OUT, bool FROM_X>
__global__ void k_gemm(const float* __restrict__ x, const float* __restrict__ W) {
    constexpr int QUADS = OUT / 4;            // 16 (OUT=64) / 8 (OUT=32)
    constexpr int RG = 256 / QUADS;           // 16 / 32 row groups
    constexpr int ROWS = RG * 4;              // 64 / 128 rows per block
    __shared__ float Ws[64 * OUT];
    __shared__ float xs[ROWS][65];            // pad kills stride-64 conflicts

    const int tid = threadIdx.x;
    const int row0 = blockIdx.x * ROWS;

    for (int i = tid; i < 64 * OUT; i += 256) Ws[i] = W[i];

    for (int i = tid; i < ROWS * 16; i += 256) {
        int r = i >> 4, c4 = i & 15;
        int row = row0 + r;
        float4 v = make_float4(0.f, 0.f, 0.f, 0.f);
        if (row < N_NODES) {
            if (FROM_X) {
                v = *(const float4*)&x[(size_t)row * 64 + c4 * 4];
            } else {
                v = *(const float4*)&g_agg[(size_t)row * 64 + c4 * 4];
                v.x = fmaxf(v.x, 0.f); v.y = fmaxf(v.y, 0.f);
                v.z = fmaxf(v.z, 0.f); v.w = fmaxf(v.w, 0.f);
            }
        }
        xs[r][c4 * 4 + 0] = v.x; xs[r][c4 * 4 + 1] = v.y;
        xs[r][c4 * 4 + 2] = v.z; xs[r][c4 * 4 + 3] = v.w;
    }
    __syncthreads();

    const int colq = tid % QUADS;
    const int rg = tid / QUADS;

    float acc[4][4];
#pragma unroll
    for (int r = 0; r < 4; r++)
#pragma unroll
        for (int c = 0; c < 4; c++) acc[r][c] = 0.f;

#pragma unroll
    for (int k = 0; k < 64; k++) {
        float4 w = *(const float4*)&Ws[k * OUT + colq * 4];
#pragma unroll
        for (int r = 0; r < 4; r++) {
            float xv = xs[rg * 4 + r][k];
            acc[r][0] = fmaf(xv, w.x, acc[r][0]);
            acc[r][1] = fmaf(xv, w.y, acc[r][1]);
            acc[r][2] = fmaf(xv, w.z, acc[r][2]);
            acc[r][3] = fmaf(xv, w.w, acc[r][3]);
        }
    }

#pragma unroll
    for (int r = 0; r < 4; r++) {
        int row = row0 + rg * 4 + r;
        if (row < N_NODES)
            *(float4*)&g_h[(size_t)row * OUT + colq * 4] =
                make_float4(acc[r][0], acc[r][1], acc[r][2], acc[r][3]);
    }
}

// ---------------- CSR aggregation: warp/node, SUBS edges in flight -----------
// out[node] = dinv_n * (dinv_n*h[node] + sum_e dinv[src_e]*h[src_e]) + b
// OUT=64: 2 half-warps x 16 lanes x float4. OUT=32: 4 quarter-warps x 8 x float4.
template <int OUT, bool TO_OUT>
__global__ void k_agg(const float* __restrict__ b, float* __restrict__ out) {
    constexpr int SUBS = (OUT == 64) ? 2 : 4;
    constexpr int LPS = 32 / SUBS;            // lanes per sub-warp (16 / 8)
    constexpr int Q = OUT / 4;                // float4s per row (16 / 8)
    const int warp = (blockIdx.x * blockDim.x + threadIdx.x) >> 5;
    const int lane = threadIdx.x & 31;
    if (warp >= N_NODES) return;
    const int node = warp;

    const int sub = lane / LPS;
    const int li = lane % LPS;
    const float4* h4 = (const float4*)g_h;

    const float dn = g_dinv[node];
    float4 acc = make_float4(0.f, 0.f, 0.f, 0.f);
    if (sub == 0) {
        float4 hv = h4[(size_t)node * Q + li];
        acc.x = dn * hv.x; acc.y = dn * hv.y;
        acc.z = dn * hv.z; acc.w = dn * hv.w;
    }

    const int beg = g_off[node];
    const int end = g_off[node + 1];
    for (int p = beg + sub; p < end; p += SUBS) {
        int s = g_csrc[p];                    // uniform within sub-warp
        float ds = g_dinv[s];
        float4 hv = h4[(size_t)s * Q + li];
        acc.x = fmaf(ds, hv.x, acc.x);
        acc.y = fmaf(ds, hv.y, acc.y);
        acc.z = fmaf(ds, hv.z, acc.z);
        acc.w = fmaf(ds, hv.w, acc.w);
    }

    // combine sub-warps (tree over xor offsets LPS, ..., 16)
#pragma unroll
    for (int off = LPS; off < 32; off <<= 1) {
        acc.x += __shfl_xor_sync(0xffffffffu, acc.x, off);
        acc.y += __shfl_xor_sync(0xffffffffu, acc.y, off);
        acc.z += __shfl_xor_sync(0xffffffffu, acc.z, off);
        acc.w += __shfl_xor_sync(0xffffffffu, acc.w, off);
    }

    if (sub == 0) {
        float4 bq = ((const float4*)b)[li];
        float4 o;
        o.x = fmaf(dn, acc.x, bq.x);
        o.y = fmaf(dn, acc.y, bq.y);
        o.z = fmaf(dn, acc.z, bq.z);
        o.w = fmaf(dn, acc.w, bq.w);
        if (TO_OUT) ((float4*)out)[(size_t)node * Q + li] = o;
        else        ((float4*)g_agg)[(size_t)node * Q + li] = o;
    }
}

// ---------------- launch: kernel launches ONLY --------------------------------
extern "C" void kernel_launch(void* const* d_in, const int* in_sizes, int n_in,
                              void* d_out, int out_size) {
    const float* x  = (const float*)d_in[0];
    const int* ei   = (const int*)d_in[1];   // int32 (JAX x64 off); int64 auto-detected
    const float* W1 = (const float*)d_in[2];
    const float* b1 = (const float*)d_in[3];
    const float* W2 = (const float*)d_in[4];
    const float* b2 = (const float*)d_in[5];
    const float* W3 = (const float*)d_in[6];
    const float* b3 = (const float*)d_in[7];
    float* out      = (float*)d_out;

    const int T = 256;
    const int gN = (N_NODES + T - 1) / T;
    const int gE = (N_EDGES + T - 1) / T;
    const int gW = (N_NODES * 32 + T - 1) / T;  // one warp per node

    // CSR build (4 launches)
    k_zero<<<gN, T>>>(ei);
    k_pre<<<gE, T>>>(ei);
    k_scan<<<1, 1024>>>();
    k_place<<<gE, T>>>();

    // Layer 1
    k_gemm<64, true><<<(N_NODES + 63) / 64, T>>>(x, W1);
    k_agg<64, false><<<gW, T>>>(b1, nullptr);

    // Layer 2
    k_gemm<64, false><<<(N_NODES + 63) / 64, T>>>(nullptr, W2);
    k_agg<64, false><<<gW, T>>>(b2, nullptr);

    // Layer 3 (OUT=32) -> harness output
    k_gemm<32, false><<<(N_NODES + 127) / 128, T>>>(nullptr, W3);
    k_agg<32, true><<<gW, T>>>(b3, out);
}